// round 7
// baseline (speedup 1.0000x reference)
#include <cuda_runtime.h>

// out = sum(x) * a * b ; x is 8192*8192 fp32, a,b device scalars.
// Single fused kernel, one full-occupancy wave: launch_bounds(256,8) pins
// regs<=32 -> 8 CTAs/SM -> grid 148*8=1184, ~33KB of LDG.128 in flight per SM
// (above the ~26KB needed to cover DRAM latency at link rate).

#define NBLOCKS 1184   // 8 CTAs/SM * 148 SMs — one balanced wave at 32 regs
#define NTHREADS 256

__device__ float g_partials[NBLOCKS];
__device__ unsigned int g_count;   // zero-init; reset by last block each run

__global__ __launch_bounds__(NTHREADS, 8) void reduce_fused(
    const float4* __restrict__ x4, int n4,
    const float* __restrict__ a, const float* __restrict__ b,
    float* __restrict__ out)
{
    const int tid = threadIdx.x;
    const int stride = NBLOCKS * NTHREADS;
    int i = blockIdx.x * NTHREADS + tid;

    // 4 independent accumulators -> 4 LDG.128 in flight per thread.
    float s0 = 0.f, s1 = 0.f, s2 = 0.f, s3 = 0.f;

    for (; i + 3 * stride < n4; i += 4 * stride) {
        float4 v0 = __ldg(&x4[i]);
        float4 v1 = __ldg(&x4[i + stride]);
        float4 v2 = __ldg(&x4[i + 2 * stride]);
        float4 v3 = __ldg(&x4[i + 3 * stride]);
        s0 += (v0.x + v0.y) + (v0.z + v0.w);
        s1 += (v1.x + v1.y) + (v1.z + v1.w);
        s2 += (v2.x + v2.y) + (v2.z + v2.w);
        s3 += (v3.x + v3.y) + (v3.z + v3.w);
    }
    for (; i < n4; i += stride) {
        float4 v = __ldg(&x4[i]);
        s0 += (v.x + v.y) + (v.z + v.w);
    }
    float s = (s0 + s1) + (s2 + s3);

    #pragma unroll
    for (int o = 16; o > 0; o >>= 1)
        s += __shfl_down_sync(0xffffffffu, s, o);

    __shared__ float sh[NTHREADS / 32];
    __shared__ bool is_last;
    if ((tid & 31) == 0) sh[tid >> 5] = s;
    __syncthreads();

    if (tid < 32) {
        float v = (tid < NTHREADS / 32) ? sh[tid] : 0.0f;
        #pragma unroll
        for (int o = 4; o > 0; o >>= 1)
            v += __shfl_down_sync(0xffffffffu, v, o);
        if (tid == 0) {
            g_partials[blockIdx.x] = v;
            __threadfence();
            unsigned int ticket = atomicAdd(&g_count, 1u);
            is_last = (ticket == NBLOCKS - 1);
        }
    }
    __syncthreads();

    if (!is_last) return;

    // Last block: reduce all partials (fixed order -> deterministic value).
    __threadfence();
    float t = 0.0f;
    for (int j = tid; j < NBLOCKS; j += NTHREADS) {
        float p;
        asm volatile("ld.global.cg.f32 %0, [%1];" : "=f"(p) : "l"(&g_partials[j]));
        t += p;
    }
    #pragma unroll
    for (int o = 16; o > 0; o >>= 1)
        t += __shfl_down_sync(0xffffffffu, t, o);

    if ((tid & 31) == 0) sh[tid >> 5] = t;
    __syncthreads();

    if (tid == 0) {
        float r = 0.0f;
        #pragma unroll
        for (int w = 0; w < NTHREADS / 32; w++) r += sh[w];
        *out = r * (*a) * (*b);
        g_count = 0;   // reset for next graph replay
    }
}

extern "C" void kernel_launch(void* const* d_in, const int* in_sizes, int n_in,
                              void* d_out, int out_size)
{
    const float* x = (const float*)d_in[0];
    const float* a = (const float*)d_in[1];
    const float* b = (const float*)d_in[2];
    float* out = (float*)d_out;

    const int n4 = in_sizes[0] >> 2;   // 16Mi float4

    reduce_fused<<<NBLOCKS, NTHREADS>>>((const float4*)x, n4, a, b, out);
}